// round 14
// baseline (speedup 1.0000x reference)
#include <cuda_runtime.h>

// ---------------------------------------------------------------------------
// ftat_BiLSTM — round 14: R13 + K2 v4 (NJ=4, phase-separated dots -> aj[4],
//                         shfl gate exchange, double-buffered h, 1 barrier/step)
// ---------------------------------------------------------------------------

namespace {
constexpr int Bn = 2048, Sn = 96, Dn = 7, Hn = 64;
constexpr int NJ = 4;
using u64 = unsigned long long;
} // namespace

__device__ float g_fa [Bn * Sn * 8];
__device__ float g_lof[Bn * Sn * Hn];
__device__ float g_lob[Bn * Sn * Hn];
__device__ float g_xg [Bn * Sn * Hn];
__device__ float g_M  [64 * 64];
__device__ float g_v  [64];

__device__ __forceinline__ float sigf(float x) { return 1.0f / (1.0f + __expf(-x)); }
__device__ __forceinline__ float tanhfast(float x) { return 1.0f - 2.0f / (__expf(2.0f * x) + 1.0f); }

__device__ __forceinline__ u64 ffma2(u64 a, u64 b, u64 c) {
    u64 d; asm("fma.rn.f32x2 %0, %1, %2, %3;" : "=l"(d) : "l"(a), "l"(b), "l"(c)); return d;
}
__device__ __forceinline__ float2 unpack2(u64 v) {
    float2 r; asm("mov.b64 {%0, %1}, %2;" : "=f"(r.x), "=f"(r.y) : "l"(v)); return r;
}
__device__ __forceinline__ u64 pack2(float lo, float hi) {
    u64 v; asm("mov.b64 %0, {%1, %2};" : "=l"(v) : "f"(lo), "f"(hi)); return v;
}
__device__ __forceinline__ u64 dup2(float x) {
    u64 v; asm("mov.b64 %0, {%1, %1};" : "=l"(v) : "f"(x)); return v;
}

__device__ __forceinline__ float dot64_pk(const float* __restrict__ x, const u64* __restrict__ w) {
    u64 a0 = 0ull, a1 = 0ull, a2 = 0ull, a3 = 0ull;
    const float4* x4 = (const float4*)x;
#pragma unroll
    for (int j = 0; j < 16; j += 2) {
        float4 v0 = x4[j], v1 = x4[j + 1];
        a0 = ffma2(pack2(v0.x, v0.y), w[2 * j + 0], a0);
        a1 = ffma2(pack2(v0.z, v0.w), w[2 * j + 1], a1);
        a2 = ffma2(pack2(v1.x, v1.y), w[2 * j + 2], a2);
        a3 = ffma2(pack2(v1.z, v1.w), w[2 * j + 3], a3);
    }
    float2 f0 = unpack2(a0), f1 = unpack2(a1), f2 = unpack2(a2), f3 = unpack2(a3);
    return ((f0.x + f0.y) + (f1.x + f1.y)) + ((f2.x + f2.y) + (f3.x + f3.y));
}

// =========================== K0 ===========================
__global__ void __launch_bounds__(256) k0_prep(const float* __restrict__ tq_w,
                                               const float* __restrict__ tk_w,
                                               const float* __restrict__ tq_b) {
    int idx = blockIdx.x * 256 + threadIdx.x;
    int e = idx >> 6, f = idx & 63;
    float acc = 0.0f;
    for (int d = 0; d < 64; d++) acc += tq_w[d * 64 + e] * tk_w[d * 64 + f];
    g_M[idx] = acc;
    if (idx < 64) {
        float a = 0.0f;
        for (int d = 0; d < 64; d++) a += tq_b[d] * tk_w[d * 64 + idx];
        g_v[idx] = a;
    }
}

// =========================== K1 ===========================
struct P1 { const float *x, *fv_w, *fv_b, *fk_w, *fk_b, *fq_w, *fq_b; };

__global__ void __launch_bounds__(128) k1_featatt(P1 P) {
    __shared__ __align__(16) float sFA[Sn * 8];
    __shared__ __align__(16) float sV[Sn * 8];
    __shared__ __align__(16) float sK[Sn * 8];
    __shared__ __align__(16) float sQ[Sn * 8];
    __shared__ float sATT[7 * 8];
    const int b = blockIdx.x, t = threadIdx.x;
    const float* x = P.x + (size_t)b * (Sn * Dn);
    for (int idx = t; idx < Sn * Dn; idx += 128) {
        int s = idx / 7, j = idx - s * 7;
        sFA[s * 8 + j] = x[idx];
    }
    if (t < Sn) sFA[t * 8 + 7] = 0.0f;
    __syncthreads();
    for (int idx = t; idx < Sn * Dn; idx += 128) {
        int s = idx / 7, i = idx - s * 7;
        float a = P.fv_b[i];
#pragma unroll
        for (int j = 0; j < 7; j++) a += sFA[s * 8 + j] * P.fv_w[i * 7 + j];
        sV[s * 8 + i] = a;
    }
    __syncthreads();
    for (int idx = t; idx < Sn * Dn; idx += 128) {
        int s = idx / 7, i = idx - s * 7;
        float a = P.fk_b[i];
#pragma unroll
        for (int j = 0; j < 7; j++) a += (sFA[s * 8 + j] + sV[s * 8 + j]) * P.fk_w[i * 7 + j];
        sK[s * 8 + i] = a;
    }
    __syncthreads();
    for (int idx = t; idx < Sn * Dn; idx += 128) {
        int s = idx / 7, i = idx - s * 7;
        float a = P.fq_b[i];
#pragma unroll
        for (int j = 0; j < 7; j++) a += (sFA[s * 8 + j] + sK[s * 8 + j]) * P.fq_w[i * 7 + j];
        sQ[s * 8 + i] = a;
    }
    __syncthreads();
    if (t < 98) {
        int pair = t >> 1, half = t & 1;
        int i = pair / 7, j = pair - (pair / 7) * 7;
        float a = 0.0f;
        int s0 = half * 48;
#pragma unroll 8
        for (int s = s0; s < s0 + 48; s++) a += sQ[s * 8 + i] * sK[s * 8 + j];
        unsigned mask = (t < 96) ? 0xffffffffu : 0x00000003u;
        a += __shfl_xor_sync(mask, a, 1);
        if (half == 0) sATT[i * 8 + j] = a;
    }
    __syncthreads();
    if (t < 7) {
        float* row = sATT + t * 8;
        float m = row[0];
#pragma unroll
        for (int j = 1; j < 7; j++) m = fmaxf(m, row[j]);
        float ssum = 0.0f;
#pragma unroll
        for (int j = 0; j < 7; j++) { float e = __expf(row[j] - m); row[j] = e; ssum += e; }
        float inv = 1.0f / ssum;
#pragma unroll
        for (int j = 0; j < 7; j++) row[j] *= inv;
    }
    __syncthreads();
    for (int idx = t; idx < Sn * Dn; idx += 128) {
        int s = idx / 7, j = idx - s * 7;
        float a = sFA[s * 8 + j];
#pragma unroll
        for (int i = 0; i < 7; i++) a += sV[s * 8 + i] * sATT[i * 8 + j];
        sFA[s * 8 + j] = tanhfast(a);
    }
    __syncthreads();
    float* fa = g_fa + (size_t)b * (Sn * 8);
    for (int idx = t; idx < Sn * 8; idx += 128) fa[idx] = sFA[idx];
}

// =========================== K2 v4: NJ=4, phase-split gates, 1 barrier/step ===========================
struct P2 {
    const float *l1f_wih, *l1f_whh, *l1f_bih, *l1f_bhh;
    const float *l1b_wih, *l1b_whh, *l1b_bih, *l1b_bhh;
    int b0;
};

__global__ void __launch_bounds__(256, 2) k2_bilstm(P2 P) {
    __shared__ __align__(16) float sFA[NJ][Sn * 8];   // 12 KB
    __shared__ __align__(16) float sWST[64 * 68];     // 17.4 KB
    __shared__ __align__(16) float sH[2][NJ][Hn];     // 2 KB
    const int dir = blockIdx.y, t = threadIdx.x;
    const int bbase = P.b0 + NJ * blockIdx.x;
    const int l = t & 31, w = t >> 5;
    const int u = w * 8 + (l >> 2);   // unit 0..63
    const int gt = l & 3;             // gate 0=i,1=f,2=g,3=o
    const int row = gt * 64 + u;

    for (int idx = t; idx < NJ * Sn * 8; idx += 256) {
        int jj = idx / (Sn * 8), r = idx - jj * (Sn * 8);
        sFA[jj][r] = g_fa[(size_t)(bbase + jj) * (Sn * 8) + r];
    }
    const float* whh = dir ? P.l1b_whh : P.l1f_whh;
    u64 wpk[32];
#pragma unroll 1
    for (int rr = 0; rr < 4; rr++) {
        for (int idx = t; idx < 64 * 64; idx += 256) {
            int rw = idx >> 6, cl = idx & 63;
            sWST[rw * 68 + cl] = whh[(rr * 64 + rw) * 64 + cl];
        }
        __syncthreads();
        if (gt == rr) {
            const u64* wr = (const u64*)(sWST + u * 68);
#pragma unroll
            for (int k = 0; k < 32; k++) wpk[k] = wr[k];
        }
        __syncthreads();
    }
    float wi[7], bias;
    {
        const float* wih = dir ? P.l1b_wih : P.l1f_wih;
#pragma unroll
        for (int j = 0; j < 7; j++) wi[j] = wih[row * 7 + j];
        bias = dir ? (P.l1b_bih[row] + P.l1b_bhh[row]) : (P.l1f_bih[row] + P.l1f_bhh[row]);
    }
    for (int idx = t; idx < NJ * Hn; idx += 256) ((float*)sH[0])[idx] = 0.0f;
    float cst[NJ];
#pragma unroll
    for (int jj = 0; jj < NJ; jj++) cst[jj] = 0.0f;
    __syncthreads();

    float* lobase = (dir ? g_lob : g_lof) + (size_t)bbase * (Sn * Hn);
    int p = 0;
    const int base = l & ~3;

#pragma unroll 1
    for (int step = 0; step < Sn; step++) {
        const int s = dir ? (Sn - 1 - step) : step;
        // Phase 1: 4 independent gate dots (cross-job ILP preserved, as in R10)
        float aj[NJ];
#pragma unroll
        for (int jj = 0; jj < NJ; jj++) {
            u64 a0 = 0ull, a1 = 0ull, a2 = 0ull, a3 = 0ull;
            const float4* h4 = (const float4*)sH[p][jj];
#pragma unroll
            for (int q = 0; q < 16; q += 2) {
                float4 v0 = h4[q], v1 = h4[q + 1];
                a0 = ffma2(pack2(v0.x, v0.y), wpk[2 * q + 0], a0);
                a1 = ffma2(pack2(v0.z, v0.w), wpk[2 * q + 1], a1);
                a2 = ffma2(pack2(v1.x, v1.y), wpk[2 * q + 2], a2);
                a3 = ffma2(pack2(v1.z, v1.w), wpk[2 * q + 3], a3);
            }
            float2 f0 = unpack2(a0), f1 = unpack2(a1), f2 = unpack2(a2), f3 = unpack2(a3);
            float a = bias + ((f0.x + f0.y) + (f1.x + f1.y)) + ((f2.x + f2.y) + (f3.x + f3.y));
            const float* fr = sFA[jj] + s * 8;
#pragma unroll
            for (int j = 0; j < 7; j++) a += fr[j] * wi[j];
            aj[jj] = a;
        }
        // Phase 2: warp-local gate exchange + activation
#pragma unroll
        for (int jj = 0; jj < NJ; jj++) {
            float fv = __shfl_sync(0xffffffffu, aj[jj], base + 1);
            float gv = __shfl_sync(0xffffffffu, aj[jj], base + 2);
            float ov = __shfl_sync(0xffffffffu, aj[jj], base + 3);
            if (gt == 0) {
                cst[jj] = sigf(fv) * cst[jj] + sigf(aj[jj]) * tanhfast(gv);
                float h = sigf(ov) * tanhfast(cst[jj]);
                sH[p ^ 1][jj][u] = h;
                lobase[(size_t)jj * (Sn * Hn) + s * Hn + u] = 0.5f * h;
            }
        }
        __syncthreads();
        p ^= 1;
    }
}

// =========================== K3 (R10 verbatim) ===========================
struct P3 {
    const float *tv_w, *tv_b;
    const float *l2_wih, *l2_bih, *l2_bhh;
    int b0;
};

namespace {
constexpr int K3_LO   = 0;
constexpr int K3_TV   = 6144;
constexpr int K3_U    = 12288;
constexpr int K3_TATT = 18816;
constexpr int K3_WST  = K3_TATT;
constexpr int K3_SA   = 28032;
constexpr int K3_SV   = 28128;
constexpr int K3_FLOATS = 28192;
constexpr int K3_NT   = 256;
}

__global__ void __launch_bounds__(256, 2) k3_tempatt(P3 P) {
    extern __shared__ float sm[];
    const int b = P.b0 + blockIdx.x, t = threadIdx.x;

    {
        const float* lf = g_lof + (size_t)b * (Sn * Hn);
        const float* lb = g_lob + (size_t)b * (Sn * Hn);
        for (int idx = t; idx < Sn * Hn; idx += K3_NT) sm[K3_LO + idx] = lf[idx] + lb[idx];
    }
    if (t < 64) sm[K3_SV + t] = g_v[t];
    __syncthreads();

    for (int idx = t; idx < 64 * 64; idx += K3_NT) {
        int row = idx >> 6, col = idx & 63;
        sm[K3_WST + row * 68 + col] = P.tv_w[idx];
    }
    if (t < 96) {
        const float4* lo4 = (const float4*)(sm + K3_LO + t * 64);
        const float4* v4 = (const float4*)(sm + K3_SV);
        float acc = 0.0f;
#pragma unroll
        for (int k = 0; k < 16; k++) {
            float4 lv = lo4[k], vv = v4[k];
            acc += lv.x * vv.x + lv.y * vv.y + lv.z * vv.z + lv.w * vv.w;
        }
        sm[K3_SA + t] = acc;
    }
    __syncthreads();

    {
        int i = t & 63, sb = t >> 6;
        u64 wpk[32];
        const u64* wr = (const u64*)(sm + K3_WST + i * 68);
#pragma unroll
        for (int k = 0; k < 32; k++) wpk[k] = wr[k];
        float bi = P.tv_b[i];
        for (int s24 = 0; s24 < 24; s24++) {
            int s = sb * 24 + s24;
            sm[K3_TV + s * 64 + i] = bi + dot64_pk(sm + K3_LO + s * 64, wpk);
        }
    }
    __syncthreads();

    for (int idx = t; idx < 64 * 64; idx += K3_NT) {
        int row = idx >> 6, col = idx & 63;
        sm[K3_WST + row * 68 + col] = g_M[idx];
    }
    __syncthreads();

    {
        int i = t & 63, sb = t >> 6;
        u64 wpk[32];
        const u64* wr = (const u64*)(sm + K3_WST + i * 68);
#pragma unroll
        for (int k = 0; k < 32; k++) wpk[k] = wr[k];
        for (int s24 = 0; s24 < 24; s24++) {
            int s = sb * 24 + s24;
            sm[K3_U + s * 68 + i] = dot64_pk(sm + K3_LO + s * 64, wpk);
        }
    }
    __syncthreads();

#pragma unroll 1
    for (int r = 0; r < 6; r++) {
        int task = r * K3_NT + t;
        int ip = task / 96, j = task - ip * 96;
        int i0 = ip * 6;
        const float4* k4p = (const float4*)(sm + K3_U + j * 68);
        u64 acc0 = 0ull, acc1 = 0ull, acc2 = 0ull, acc3 = 0ull, acc4 = 0ull, acc5 = 0ull;
#pragma unroll
        for (int d4 = 0; d4 < 16; d4++) {
            float4 kv = k4p[d4];
            u64 k01 = pack2(kv.x, kv.y), k23 = pack2(kv.z, kv.w);
            float4 q0 = *(const float4*)(sm + K3_LO + (i0 + 0) * 64 + d4 * 4);
            float4 q1 = *(const float4*)(sm + K3_LO + (i0 + 1) * 64 + d4 * 4);
            float4 q2 = *(const float4*)(sm + K3_LO + (i0 + 2) * 64 + d4 * 4);
            float4 q3 = *(const float4*)(sm + K3_LO + (i0 + 3) * 64 + d4 * 4);
            float4 q4 = *(const float4*)(sm + K3_LO + (i0 + 4) * 64 + d4 * 4);
            float4 q5 = *(const float4*)(sm + K3_LO + (i0 + 5) * 64 + d4 * 4);
            acc0 = ffma2(pack2(q0.x, q0.y), k01, acc0); acc0 = ffma2(pack2(q0.z, q0.w), k23, acc0);
            acc1 = ffma2(pack2(q1.x, q1.y), k01, acc1); acc1 = ffma2(pack2(q1.z, q1.w), k23, acc1);
            acc2 = ffma2(pack2(q2.x, q2.y), k01, acc2); acc2 = ffma2(pack2(q2.z, q2.w), k23, acc2);
            acc3 = ffma2(pack2(q3.x, q3.y), k01, acc3); acc3 = ffma2(pack2(q3.z, q3.w), k23, acc3);
            acc4 = ffma2(pack2(q4.x, q4.y), k01, acc4); acc4 = ffma2(pack2(q4.z, q4.w), k23, acc4);
            acc5 = ffma2(pack2(q5.x, q5.y), k01, acc5); acc5 = ffma2(pack2(q5.z, q5.w), k23, acc5);
        }
        float aj = sm[K3_SA + j];
        float2 f0 = unpack2(acc0), f1 = unpack2(acc1), f2 = unpack2(acc2);
        float2 f3 = unpack2(acc3), f4 = unpack2(acc4), f5 = unpack2(acc5);
        sm[K3_TATT + (i0 + 0) * 96 + j] = f0.x + f0.y + aj;
        sm[K3_TATT + (i0 + 1) * 96 + j] = f1.x + f1.y + aj;
        sm[K3_TATT + (i0 + 2) * 96 + j] = f2.x + f2.y + aj;
        sm[K3_TATT + (i0 + 3) * 96 + j] = f3.x + f3.y + aj;
        sm[K3_TATT + (i0 + 4) * 96 + j] = f4.x + f4.y + aj;
        sm[K3_TATT + (i0 + 5) * 96 + j] = f5.x + f5.y + aj;
    }
    __syncthreads();

    {
        int w = t >> 5, lane = t & 31;
        for (int rr = 0; rr < 12; rr++) {
            int i = w * 12 + rr;
            float* row = sm + K3_TATT + i * 96;
            float v0 = row[lane], v1 = row[lane + 32], v2 = row[lane + 64];
            float m = fmaxf(v0, fmaxf(v1, v2));
#pragma unroll
            for (int off = 16; off > 0; off >>= 1) m = fmaxf(m, __shfl_xor_sync(0xffffffffu, m, off));
            float e0 = __expf(v0 - m), e1 = __expf(v1 - m), e2 = __expf(v2 - m);
            float ssum = e0 + e1 + e2;
#pragma unroll
            for (int off = 16; off > 0; off >>= 1) ssum += __shfl_xor_sync(0xffffffffu, ssum, off);
            float inv = 1.0f / ssum;
            row[lane] = e0 * inv; row[lane + 32] = e1 * inv; row[lane + 64] = e2 * inv;
        }
    }
    __syncthreads();

    {
        int dp = t & 31, wb = t >> 5;
        const float* tvcol = sm + K3_TV + 2 * dp;
#pragma unroll 1
        for (int i3 = 0; i3 < 2; i3++) {
            int i0 = wb * 12 + 6 * i3;
            const float* tat = sm + K3_TATT + i0 * 96;
            u64 a0 = 0ull, a1 = 0ull, a2 = 0ull, a3 = 0ull, a4 = 0ull, a5 = 0ull;
            u64 b0 = 0ull, b1 = 0ull, b2 = 0ull, b3 = 0ull, b4 = 0ull, b5 = 0ull;
#pragma unroll 4
            for (int j = 0; j < 96; j += 2) {
                u64 tv0 = *(const u64*)(tvcol + j * 64);
                u64 tv1 = *(const u64*)(tvcol + (j + 1) * 64);
                a0 = ffma2(dup2(tat[0 * 96 + j]), tv0, a0);  b0 = ffma2(dup2(tat[0 * 96 + j + 1]), tv1, b0);
                a1 = ffma2(dup2(tat[1 * 96 + j]), tv0, a1);  b1 = ffma2(dup2(tat[1 * 96 + j + 1]), tv1, b1);
                a2 = ffma2(dup2(tat[2 * 96 + j]), tv0, a2);  b2 = ffma2(dup2(tat[2 * 96 + j + 1]), tv1, b2);
                a3 = ffma2(dup2(tat[3 * 96 + j]), tv0, a3);  b3 = ffma2(dup2(tat[3 * 96 + j + 1]), tv1, b3);
                a4 = ffma2(dup2(tat[4 * 96 + j]), tv0, a4);  b4 = ffma2(dup2(tat[4 * 96 + j + 1]), tv1, b4);
                a5 = ffma2(dup2(tat[5 * 96 + j]), tv0, a5);  b5 = ffma2(dup2(tat[5 * 96 + j + 1]), tv1, b5);
            }
            float2 fa0 = unpack2(a0), fb0 = unpack2(b0);
            float2 fa1 = unpack2(a1), fb1 = unpack2(b1);
            float2 fa2 = unpack2(a2), fb2 = unpack2(b2);
            float2 fa3 = unpack2(a3), fb3 = unpack2(b3);
            float2 fa4 = unpack2(a4), fb4 = unpack2(b4);
            float2 fa5 = unpack2(a5), fb5 = unpack2(b5);
            sm[K3_LO + (i0 + 0) * 64 + 2 * dp + 0] = tanhfast(fa0.x + fb0.x);
            sm[K3_LO + (i0 + 0) * 64 + 2 * dp + 1] = tanhfast(fa0.y + fb0.y);
            sm[K3_LO + (i0 + 1) * 64 + 2 * dp + 0] = tanhfast(fa1.x + fb1.x);
            sm[K3_LO + (i0 + 1) * 64 + 2 * dp + 1] = tanhfast(fa1.y + fb1.y);
            sm[K3_LO + (i0 + 2) * 64 + 2 * dp + 0] = tanhfast(fa2.x + fb2.x);
            sm[K3_LO + (i0 + 2) * 64 + 2 * dp + 1] = tanhfast(fa2.y + fb2.y);
            sm[K3_LO + (i0 + 3) * 64 + 2 * dp + 0] = tanhfast(fa3.x + fb3.x);
            sm[K3_LO + (i0 + 3) * 64 + 2 * dp + 1] = tanhfast(fa3.y + fb3.y);
            sm[K3_LO + (i0 + 4) * 64 + 2 * dp + 0] = tanhfast(fa4.x + fb4.x);
            sm[K3_LO + (i0 + 4) * 64 + 2 * dp + 1] = tanhfast(fa4.y + fb4.y);
            sm[K3_LO + (i0 + 5) * 64 + 2 * dp + 0] = tanhfast(fa5.x + fb5.x);
            sm[K3_LO + (i0 + 5) * 64 + 2 * dp + 1] = tanhfast(fa5.y + fb5.y);
        }
    }
    __syncthreads();

    for (int idx = t; idx < 64 * 64; idx += K3_NT) {
        int row = idx >> 6, col = idx & 63;
        sm[K3_U + row * 68 + col] = P.l2_wih[idx];
    }
    __syncthreads();
    {
        int g2 = t & 63, sb = t >> 6;
        u64 wpk[32];
        const u64* wr = (const u64*)(sm + K3_U + g2 * 68);
#pragma unroll
        for (int k = 0; k < 32; k++) wpk[k] = wr[k];
        float bi = P.l2_bih[g2] + P.l2_bhh[g2];
        float* xgp = g_xg + (size_t)b * (Sn * Hn);
        for (int s24 = 0; s24 < 24; s24++) {
            int s = sb * 24 + s24;
            xgp[s * 64 + g2] = bi + dot64_pk(sm + K3_LO + s * 64, wpk);
        }
    }
}

// =========================== K4 ===========================
struct P4 { const float *l2_whh, *fc_w, *fc_b; float* out; int b0; };

__global__ void __launch_bounds__(256) k4_rec(P4 P) {
    const int warp = P.b0 + blockIdx.x * 8 + (threadIdx.x >> 5);
    const int lane = threadIdx.x & 31;
    const float* xg = g_xg + (size_t)warp * (Sn * Hn);
    float* outp = P.out + (size_t)warp * (Sn * Dn);

    u64 w0[8], w1[8];
    {
        const u64* r0 = (const u64*)(P.l2_whh + lane * 16);
        const u64* r1 = (const u64*)(P.l2_whh + (lane + 32) * 16);
#pragma unroll
        for (int k = 0; k < 8; k++) { w0[k] = r0[k]; w1[k] = r1[k]; }
    }
    u64 wfc[8]; float fcb;
    {
        int fl = lane < 7 ? lane : 0;
        const u64* rf = (const u64*)(P.fc_w + fl * 16);
#pragma unroll
        for (int k = 0; k < 8; k++) wfc[k] = rf[k];
        fcb = P.fc_b[fl];
    }

    float h = 0.0f, c = 0.0f;
    float xg0 = xg[lane], xg1 = xg[32 + lane];

#pragma unroll 1
    for (int s = 0; s < Sn; s++) {
        u64 acc0 = 0ull, acc1 = 0ull, accf = 0ull;
#pragma unroll
        for (int m = 0; m < 8; m++) {
            float ha = __shfl_sync(0xffffffffu, h, 2 * m);
            float hb = __shfl_sync(0xffffffffu, h, 2 * m + 1);
            u64 hp = pack2(ha, hb);
            acc0 = ffma2(hp, w0[m], acc0);
            acc1 = ffma2(hp, w1[m], acc1);
            accf = ffma2(hp, wfc[m], accf);
        }
        if (s > 0 && lane < 7) {
            float2 ff = unpack2(accf);
            outp[(s - 1) * 7 + lane] = fcb + ff.x + ff.y;
        }
        float2 f0 = unpack2(acc0), f1 = unpack2(acc1);
        float a0 = xg0 + f0.x + f0.y;
        float a1 = xg1 + f1.x + f1.y;
        if (s + 1 < Sn) {
            xg0 = xg[(s + 1) * 64 + lane];
            xg1 = xg[(s + 1) * 64 + 32 + lane];
        }
        int j = lane & 15;
        float iv = __shfl_sync(0xffffffffu, a0, j);
        float fv = __shfl_sync(0xffffffffu, a0, j + 16);
        float gv = __shfl_sync(0xffffffffu, a1, j);
        float ov = __shfl_sync(0xffffffffu, a1, j + 16);
        c = sigf(fv) * c + sigf(iv) * tanhfast(gv);
        h = sigf(ov) * tanhfast(c);
    }
    {
        u64 accf = 0ull;
#pragma unroll
        for (int m = 0; m < 8; m++) {
            float ha = __shfl_sync(0xffffffffu, h, 2 * m);
            float hb = __shfl_sync(0xffffffffu, h, 2 * m + 1);
            accf = ffma2(pack2(ha, hb), wfc[m], accf);
        }
        if (lane < 7) {
            float2 ff = unpack2(accf);
            outp[95 * 7 + lane] = fcb + ff.x + ff.y;
        }
    }
}

// =========================== launch ===========================
extern "C" void kernel_launch(void* const* d_in, const int* in_sizes, int n_in,
                              void* d_out, int out_size) {
    P1 p1; P2 p2; P3 p3; P4 p4;
    p1.x       = (const float*)d_in[0];
    p1.fv_w    = (const float*)d_in[1];  p1.fv_b = (const float*)d_in[2];
    p1.fk_w    = (const float*)d_in[3];  p1.fk_b = (const float*)d_in[4];
    p1.fq_w    = (const float*)d_in[5];  p1.fq_b = (const float*)d_in[6];
    p2.l1f_wih = (const float*)d_in[7];  p2.l1f_whh = (const float*)d_in[8];
    p2.l1f_bih = (const float*)d_in[9];  p2.l1f_bhh = (const float*)d_in[10];
    p2.l1b_wih = (const float*)d_in[11]; p2.l1b_whh = (const float*)d_in[12];
    p2.l1b_bih = (const float*)d_in[13]; p2.l1b_bhh = (const float*)d_in[14];
    p3.tv_w    = (const float*)d_in[15]; p3.tv_b = (const float*)d_in[16];
    const float* tk_w = (const float*)d_in[17];
    const float* tq_w = (const float*)d_in[19];
    const float* tq_b = (const float*)d_in[20];
    p3.l2_wih  = (const float*)d_in[21];
    p3.l2_bih  = (const float*)d_in[23]; p3.l2_bhh = (const float*)d_in[24];
    p4.l2_whh  = (const float*)d_in[22];
    p4.fc_w    = (const float*)d_in[25]; p4.fc_b = (const float*)d_in[26];
    p4.out     = (float*)d_out;

    static cudaStream_t s1 = nullptr, s2 = nullptr;
    static cudaEvent_t eF = nullptr, eA = nullptr, eB = nullptr;
    if (s1 == nullptr) {
        cudaStreamCreateWithFlags(&s1, cudaStreamNonBlocking);
        cudaStreamCreateWithFlags(&s2, cudaStreamNonBlocking);
        cudaEventCreateWithFlags(&eF, cudaEventDisableTiming);
        cudaEventCreateWithFlags(&eA, cudaEventDisableTiming);
        cudaEventCreateWithFlags(&eB, cudaEventDisableTiming);
        cudaFuncSetAttribute(k3_tempatt, cudaFuncAttributeMaxDynamicSharedMemorySize,
                             K3_FLOATS * (int)sizeof(float));
    }

    const int Bh = Bn / 2;
    const int smem3 = K3_FLOATS * (int)sizeof(float);

    k0_prep<<<16, 256>>>(tq_w, tk_w, tq_b);
    k1_featatt<<<Bn, 128>>>(p1);
    cudaEventRecord(eF, 0);

    cudaStreamWaitEvent(s1, eF, 0);
    cudaStreamWaitEvent(s2, eF, 0);

    P2 p2a = p2; p2a.b0 = 0;
    P2 p2b = p2; p2b.b0 = Bh;
    P3 p3a = p3; p3a.b0 = 0;
    P3 p3b = p3; p3b.b0 = Bh;
    P4 p4a = p4; p4a.b0 = 0;
    P4 p4b = p4; p4b.b0 = Bh;

    k2_bilstm<<<dim3(Bh / NJ, 2), 256, 0, s1>>>(p2a);
    k2_bilstm<<<dim3(Bh / NJ, 2), 256, 0, s2>>>(p2b);
    k3_tempatt<<<Bh, K3_NT, smem3, s1>>>(p3a);
    k3_tempatt<<<Bh, K3_NT, smem3, s2>>>(p3b);
    k4_rec<<<Bh / 8, 256, 0, s1>>>(p4a);
    k4_rec<<<Bh / 8, 256, 0, s2>>>(p4b);
    cudaEventRecord(eA, s1);
    cudaEventRecord(eB, s2);

    cudaStreamWaitEvent(0, eA, 0);
    cudaStreamWaitEvent(0, eB, 0);
}

// round 15
// speedup vs baseline: 1.3969x; 1.3969x over previous
#include <cuda_runtime.h>

// ---------------------------------------------------------------------------
// ftat_BiLSTM — round 15: revert to round-10 configuration (measured best,
// 1011.5 us). K0 prep + K1 feature attention + K2 BiLSTM (4 jobs/CTA, smem
// gate exchange) + K3 fused temporal attention (tatt = lo·(M lo)+a, 2 CTA/SM)
// + K4 warp-per-batch LSTM2+FC, two-stream half-batch pipelining.
// ---------------------------------------------------------------------------

namespace {
constexpr int Bn = 2048, Sn = 96, Dn = 7, Hn = 64;
constexpr int NJ = 4;
using u64 = unsigned long long;
} // namespace

__device__ float g_fa [Bn * Sn * 8];
__device__ float g_lof[Bn * Sn * Hn];
__device__ float g_lob[Bn * Sn * Hn];
__device__ float g_xg [Bn * Sn * Hn];
__device__ float g_M  [64 * 64];   // Wq^T Wk
__device__ float g_v  [64];        // Wk^T bq

__device__ __forceinline__ float sigf(float x) { return 1.0f / (1.0f + __expf(-x)); }
__device__ __forceinline__ float tanhfast(float x) { return 1.0f - 2.0f / (__expf(2.0f * x) + 1.0f); }

__device__ __forceinline__ u64 ffma2(u64 a, u64 b, u64 c) {
    u64 d; asm("fma.rn.f32x2 %0, %1, %2, %3;" : "=l"(d) : "l"(a), "l"(b), "l"(c)); return d;
}
__device__ __forceinline__ float2 unpack2(u64 v) {
    float2 r; asm("mov.b64 {%0, %1}, %2;" : "=f"(r.x), "=f"(r.y) : "l"(v)); return r;
}
__device__ __forceinline__ u64 pack2(float lo, float hi) {
    u64 v; asm("mov.b64 %0, {%1, %2};" : "=l"(v) : "f"(lo), "f"(hi)); return v;
}
__device__ __forceinline__ u64 dup2(float x) {
    u64 v; asm("mov.b64 %0, {%1, %1};" : "=l"(v) : "f"(x)); return v;
}

__device__ __forceinline__ float dot64_pk(const float* __restrict__ x, const u64* __restrict__ w) {
    u64 a0 = 0ull, a1 = 0ull, a2 = 0ull, a3 = 0ull;
    const float4* x4 = (const float4*)x;
#pragma unroll
    for (int j = 0; j < 16; j += 2) {
        float4 v0 = x4[j], v1 = x4[j + 1];
        a0 = ffma2(pack2(v0.x, v0.y), w[2 * j + 0], a0);
        a1 = ffma2(pack2(v0.z, v0.w), w[2 * j + 1], a1);
        a2 = ffma2(pack2(v1.x, v1.y), w[2 * j + 2], a2);
        a3 = ffma2(pack2(v1.z, v1.w), w[2 * j + 3], a3);
    }
    float2 f0 = unpack2(a0), f1 = unpack2(a1), f2 = unpack2(a2), f3 = unpack2(a3);
    return ((f0.x + f0.y) + (f1.x + f1.y)) + ((f2.x + f2.y) + (f3.x + f3.y));
}

// =========================== K0: precompute M = Wq^T Wk, v = Wk^T bq ===========================
__global__ void __launch_bounds__(256) k0_prep(const float* __restrict__ tq_w,
                                               const float* __restrict__ tk_w,
                                               const float* __restrict__ tq_b) {
    int idx = blockIdx.x * 256 + threadIdx.x;   // 0..4095
    int e = idx >> 6, f = idx & 63;
    float acc = 0.0f;
    for (int d = 0; d < 64; d++) acc += tq_w[d * 64 + e] * tk_w[d * 64 + f];
    g_M[idx] = acc;
    if (idx < 64) {
        float a = 0.0f;
        for (int d = 0; d < 64; d++) a += tq_b[d] * tk_w[d * 64 + idx];
        g_v[idx] = a;
    }
}

// =========================== K1: feature attention ===========================
struct P1 { const float *x, *fv_w, *fv_b, *fk_w, *fk_b, *fq_w, *fq_b; };

__global__ void __launch_bounds__(128) k1_featatt(P1 P) {
    __shared__ __align__(16) float sFA[Sn * 8];
    __shared__ __align__(16) float sV[Sn * 8];
    __shared__ __align__(16) float sK[Sn * 8];
    __shared__ __align__(16) float sQ[Sn * 8];
    __shared__ float sATT[7 * 8];
    const int b = blockIdx.x, t = threadIdx.x;
    const float* x = P.x + (size_t)b * (Sn * Dn);
    for (int idx = t; idx < Sn * Dn; idx += 128) {
        int s = idx / 7, j = idx - s * 7;
        sFA[s * 8 + j] = x[idx];
    }
    if (t < Sn) sFA[t * 8 + 7] = 0.0f;
    __syncthreads();
    for (int idx = t; idx < Sn * Dn; idx += 128) {
        int s = idx / 7, i = idx - s * 7;
        float a = P.fv_b[i];
#pragma unroll
        for (int j = 0; j < 7; j++) a += sFA[s * 8 + j] * P.fv_w[i * 7 + j];
        sV[s * 8 + i] = a;
    }
    __syncthreads();
    for (int idx = t; idx < Sn * Dn; idx += 128) {
        int s = idx / 7, i = idx - s * 7;
        float a = P.fk_b[i];
#pragma unroll
        for (int j = 0; j < 7; j++) a += (sFA[s * 8 + j] + sV[s * 8 + j]) * P.fk_w[i * 7 + j];
        sK[s * 8 + i] = a;
    }
    __syncthreads();
    for (int idx = t; idx < Sn * Dn; idx += 128) {
        int s = idx / 7, i = idx - s * 7;
        float a = P.fq_b[i];
#pragma unroll
        for (int j = 0; j < 7; j++) a += (sFA[s * 8 + j] + sK[s * 8 + j]) * P.fq_w[i * 7 + j];
        sQ[s * 8 + i] = a;
    }
    __syncthreads();
    if (t < 49) {
        int i = t / 7, j = t - (t / 7) * 7;
        float a = 0.0f;
        for (int s = 0; s < Sn; s++) a += sQ[s * 8 + i] * sK[s * 8 + j];
        sATT[i * 8 + j] = a;
    }
    __syncthreads();
    if (t < 7) {
        float* row = sATT + t * 8;
        float m = row[0];
#pragma unroll
        for (int j = 1; j < 7; j++) m = fmaxf(m, row[j]);
        float ssum = 0.0f;
#pragma unroll
        for (int j = 0; j < 7; j++) { float e = __expf(row[j] - m); row[j] = e; ssum += e; }
        float inv = 1.0f / ssum;
#pragma unroll
        for (int j = 0; j < 7; j++) row[j] *= inv;
    }
    __syncthreads();
    for (int idx = t; idx < Sn * Dn; idx += 128) {
        int s = idx / 7, j = idx - s * 7;
        float a = sFA[s * 8 + j];
#pragma unroll
        for (int i = 0; i < 7; i++) a += sV[s * 8 + i] * sATT[i * 8 + j];
        sFA[s * 8 + j] = tanhfast(a);
    }
    __syncthreads();
    float* fa = g_fa + (size_t)b * (Sn * 8);
    for (int idx = t; idx < Sn * 8; idx += 128) fa[idx] = sFA[idx];
}

// =========================== K2: BiLSTM, 4 jobs per CTA ===========================
struct P2 {
    const float *l1f_wih, *l1f_whh, *l1f_bih, *l1f_bhh;
    const float *l1b_wih, *l1b_whh, *l1b_bih, *l1b_bhh;
    int b0;
};

__global__ void __launch_bounds__(256, 2) k2_bilstm(P2 P) {
    __shared__ __align__(16) float sFA[NJ][Sn * 8];
    __shared__ __align__(16) float sWST[64 * 68];
    __shared__ __align__(16) float sH[NJ][Hn];
    __shared__ float sG[NJ][256];
    const int dir = blockIdx.y, t = threadIdx.x;
    const int bbase = P.b0 + NJ * blockIdx.x;

    for (int idx = t; idx < NJ * Sn * 8; idx += 256) {
        int jj = idx / (Sn * 8), r = idx - jj * (Sn * 8);
        sFA[jj][r] = g_fa[(size_t)(bbase + jj) * (Sn * 8) + r];
    }
    const float* whh = dir ? P.l1b_whh : P.l1f_whh;
    u64 wpk[32];
#pragma unroll 1
    for (int r = 0; r < 4; r++) {
        for (int idx = t; idx < 64 * 64; idx += 256) {
            int row = idx >> 6, col = idx & 63;
            sWST[row * 68 + col] = whh[(r * 64 + row) * 64 + col];
        }
        __syncthreads();
        if ((t >> 6) == r) {
            const u64* wr = (const u64*)(sWST + (t & 63) * 68);
#pragma unroll
            for (int k = 0; k < 32; k++) wpk[k] = wr[k];
        }
        __syncthreads();
    }
    float wi[7], bias;
    {
        const float* wih = dir ? P.l1b_wih : P.l1f_wih;
#pragma unroll
        for (int j = 0; j < 7; j++) wi[j] = wih[t * 7 + j];
        bias = dir ? (P.l1b_bih[t] + P.l1b_bhh[t]) : (P.l1f_bih[t] + P.l1f_bhh[t]);
    }
    const int jjA = t >> 6, uA = t & 63;
    ((float*)sH)[t] = 0.0f;
    float c1 = 0.0f;
    __syncthreads();

    float* loA = (dir ? g_lob : g_lof) + (size_t)(bbase + jjA) * (Sn * Hn);

#pragma unroll 1
    for (int step = 0; step < Sn; step++) {
        const int s = dir ? (Sn - 1 - step) : step;
#pragma unroll
        for (int jj = 0; jj < NJ; jj++) {
            u64 a0 = 0ull, a1 = 0ull, a2 = 0ull, a3 = 0ull;
            const float4* h4 = (const float4*)sH[jj];
#pragma unroll
            for (int q = 0; q < 16; q += 2) {
                float4 v0 = h4[q], v1 = h4[q + 1];
                a0 = ffma2(pack2(v0.x, v0.y), wpk[2 * q + 0], a0);
                a1 = ffma2(pack2(v0.z, v0.w), wpk[2 * q + 1], a1);
                a2 = ffma2(pack2(v1.x, v1.y), wpk[2 * q + 2], a2);
                a3 = ffma2(pack2(v1.z, v1.w), wpk[2 * q + 3], a3);
            }
            float2 f0 = unpack2(a0), f1 = unpack2(a1), f2 = unpack2(a2), f3 = unpack2(a3);
            float a = bias + ((f0.x + f0.y) + (f1.x + f1.y)) + ((f2.x + f2.y) + (f3.x + f3.y));
            const float* fr = sFA[jj] + s * 8;
#pragma unroll
            for (int j = 0; j < 7; j++) a += fr[j] * wi[j];
            sG[jj][t] = a;
        }
        __syncthreads();
        {
            float gi = sG[jjA][uA], gf = sG[jjA][64 + uA];
            float gc = sG[jjA][128 + uA], go = sG[jjA][192 + uA];
            c1 = sigf(gf) * c1 + sigf(gi) * tanhfast(gc);
            float h = sigf(go) * tanhfast(c1);
            sH[jjA][uA] = h;
            loA[s * Hn + uA] = 0.5f * h;
        }
        __syncthreads();
    }
}

// =========================== K3: temporal attention + LSTM2-input GEMM ===========================
struct P3 {
    const float *tv_w, *tv_b;
    const float *l2_wih, *l2_bih, *l2_bhh;
    int b0;
};

namespace {
constexpr int K3_LO   = 0;        // 96 x 64   (lo; later "to")
constexpr int K3_TV   = 6144;     // 96 x 64
constexpr int K3_U    = 12288;    // 96 x 68   (u = M @ lo; later l2_wih staging)
constexpr int K3_TATT = 18816;    // 96 x 96   (WST staging overlays, disjoint phases)
constexpr int K3_WST  = K3_TATT;
constexpr int K3_SA   = 28032;    // 96
constexpr int K3_SV   = 28128;    // 64
constexpr int K3_FLOATS = 28192;  // 112768 bytes -> 2 CTAs/SM
constexpr int K3_NT   = 256;
}

__global__ void __launch_bounds__(256, 2) k3_tempatt(P3 P) {
    extern __shared__ float sm[];
    const int b = P.b0 + blockIdx.x, t = threadIdx.x;

    {
        const float* lf = g_lof + (size_t)b * (Sn * Hn);
        const float* lb = g_lob + (size_t)b * (Sn * Hn);
        for (int idx = t; idx < Sn * Hn; idx += K3_NT) sm[K3_LO + idx] = lf[idx] + lb[idx];
    }
    if (t < 64) sm[K3_SV + t] = g_v[t];
    __syncthreads();

    // stage tv_w; concurrently a[s] = lo_s . v
    for (int idx = t; idx < 64 * 64; idx += K3_NT) {
        int row = idx >> 6, col = idx & 63;
        sm[K3_WST + row * 68 + col] = P.tv_w[idx];
    }
    if (t < 96) {
        const float4* lo4 = (const float4*)(sm + K3_LO + t * 64);
        const float4* v4 = (const float4*)(sm + K3_SV);
        float acc = 0.0f;
#pragma unroll
        for (int k = 0; k < 16; k++) {
            float4 l = lo4[k], vv = v4[k];
            acc += l.x * vv.x + l.y * vv.y + l.z * vv.z + l.w * vv.w;
        }
        sm[K3_SA + t] = acc;
    }
    __syncthreads();

    // tv = lo @ tv_w^T + tv_b
    {
        int i = t & 63, sb = t >> 6;
        u64 wpk[32];
        const u64* wr = (const u64*)(sm + K3_WST + i * 68);
#pragma unroll
        for (int k = 0; k < 32; k++) wpk[k] = wr[k];
        float bi = P.tv_b[i];
        for (int s24 = 0; s24 < 24; s24++) {
            int s = sb * 24 + s24;
            sm[K3_TV + s * 64 + i] = bi + dot64_pk(sm + K3_LO + s * 64, wpk);
        }
    }
    __syncthreads();

    // stage M
    for (int idx = t; idx < 64 * 64; idx += K3_NT) {
        int row = idx >> 6, col = idx & 63;
        sm[K3_WST + row * 68 + col] = g_M[idx];
    }
    __syncthreads();

    // u = lo @ M^T
    {
        int i = t & 63, sb = t >> 6;
        u64 wpk[32];
        const u64* wr = (const u64*)(sm + K3_WST + i * 68);
#pragma unroll
        for (int k = 0; k < 32; k++) wpk[k] = wr[k];
        for (int s24 = 0; s24 < 24; s24++) {
            int s = sb * 24 + s24;
            sm[K3_U + s * 68 + i] = dot64_pk(sm + K3_LO + s * 64, wpk);
        }
    }
    __syncthreads();

    // tatt[i][j] = lo_i . u_j + a_j   (6x1 tile)
#pragma unroll 1
    for (int r = 0; r < 6; r++) {
        int task = r * K3_NT + t;
        int ip = task / 96, j = task - ip * 96;
        int i0 = ip * 6;
        const float4* k4p = (const float4*)(sm + K3_U + j * 68);
        u64 acc0 = 0ull, acc1 = 0ull, acc2 = 0ull, acc3 = 0ull, acc4 = 0ull, acc5 = 0ull;
#pragma unroll
        for (int d4 = 0; d4 < 16; d4++) {
            float4 kv = k4p[d4];
            u64 k01 = pack2(kv.x, kv.y), k23 = pack2(kv.z, kv.w);
            float4 q0 = *(const float4*)(sm + K3_LO + (i0 + 0) * 64 + d4 * 4);
            float4 q1 = *(const float4*)(sm + K3_LO + (i0 + 1) * 64 + d4 * 4);
            float4 q2 = *(const float4*)(sm + K3_LO + (i0 + 2) * 64 + d4 * 4);
            float4 q3 = *(const float4*)(sm + K3_LO + (i0 + 3) * 64 + d4 * 4);
            float4 q4 = *(const float4*)(sm + K3_LO + (i0 + 4) * 64 + d4 * 4);
            float4 q5 = *(const float4*)(sm + K3_LO + (i0 + 5) * 64 + d4 * 4);
            acc0 = ffma2(pack2(q0.x, q0.y), k01, acc0); acc0 = ffma2(pack2(q0.z, q0.w), k23, acc0);
            acc1 = ffma2(pack2(q1.x, q1.y), k01, acc1); acc1 = ffma2(pack2(q1.z, q1.w), k23, acc1);
            acc2 = ffma2(pack2(q2.x, q2.y), k01, acc2); acc2 = ffma2(pack2(q2.z, q2.w), k23, acc2);
            acc3 = ffma2(pack2(q3.x, q3.y), k01, acc3); acc3 = ffma2(pack2(q3.z, q3.w), k23, acc3);
            acc4 = ffma2(pack2(q4.x, q4.y), k01, acc4); acc4 = ffma2(pack2(q4.z, q4.w), k23, acc4);
            acc5 = ffma2(pack2(q5.x, q5.y), k01, acc5); acc5 = ffma2(pack2(q5.z, q5.w), k23, acc5);
        }
        float aj = sm[K3_SA + j];
        float2 f0 = unpack2(acc0), f1 = unpack2(acc1), f2 = unpack2(acc2);
        float2 f3 = unpack2(acc3), f4 = unpack2(acc4), f5 = unpack2(acc5);
        sm[K3_TATT + (i0 + 0) * 96 + j] = f0.x + f0.y + aj;
        sm[K3_TATT + (i0 + 1) * 96 + j] = f1.x + f1.y + aj;
        sm[K3_TATT + (i0 + 2) * 96 + j] = f2.x + f2.y + aj;
        sm[K3_TATT + (i0 + 3) * 96 + j] = f3.x + f3.y + aj;
        sm[K3_TATT + (i0 + 4) * 96 + j] = f4.x + f4.y + aj;
        sm[K3_TATT + (i0 + 5) * 96 + j] = f5.x + f5.y + aj;
    }
    __syncthreads();

    // softmax rows: 8 warps x 12 rows
    {
        int w = t >> 5, lane = t & 31;
        for (int rr = 0; rr < 12; rr++) {
            int i = w * 12 + rr;
            float* row = sm + K3_TATT + i * 96;
            float v0 = row[lane], v1 = row[lane + 32], v2 = row[lane + 64];
            float m = fmaxf(v0, fmaxf(v1, v2));
#pragma unroll
            for (int off = 16; off > 0; off >>= 1) m = fmaxf(m, __shfl_xor_sync(0xffffffffu, m, off));
            float e0 = __expf(v0 - m), e1 = __expf(v1 - m), e2 = __expf(v2 - m);
            float ssum = e0 + e1 + e2;
#pragma unroll
            for (int off = 16; off > 0; off >>= 1) ssum += __shfl_xor_sync(0xffffffffu, ssum, off);
            float inv = 1.0f / ssum;
            row[lane] = e0 * inv; row[lane + 32] = e1 * inv; row[lane + 64] = e2 * inv;
        }
    }
    __syncthreads();

    // to = tanh(tatt @ tv) -> K3_LO
    {
        int dp = t & 31, wb = t >> 5;
        const float* tvcol = sm + K3_TV + 2 * dp;
#pragma unroll 1
        for (int i3 = 0; i3 < 2; i3++) {
            int i0 = wb * 12 + 6 * i3;
            const float* tat = sm + K3_TATT + i0 * 96;
            u64 a0 = 0ull, a1 = 0ull, a2 = 0ull, a3 = 0ull, a4 = 0ull, a5 = 0ull;
            u64 b0 = 0ull, b1 = 0ull, b2 = 0ull, b3 = 0ull, b4 = 0ull, b5 = 0ull;
#pragma unroll 4
            for (int j = 0; j < 96; j += 2) {
                u64 tv0 = *(const u64*)(tvcol + j * 64);
                u64 tv1 = *(const u64*)(tvcol + (j + 1) * 64);
                a0 = ffma2(dup2(tat[0 * 96 + j]), tv0, a0);  b0 = ffma2(dup2(tat[0 * 96 + j + 1]), tv1, b0);
                a1 = ffma2(dup2(tat[1 * 96 + j]), tv0, a1);  b1 = ffma2(dup2(tat[1 * 96 + j + 1]), tv1, b1);
                a2 = ffma2(dup2(tat[2 * 96 + j]), tv0, a2);  b2 = ffma2(dup2(tat[2 * 96 + j + 1]), tv1, b2);
                a3 = ffma2(dup2(tat[3 * 96 + j]), tv0, a3);  b3 = ffma2(dup2(tat[3 * 96 + j + 1]), tv1, b3);
                a4 = ffma2(dup2(tat[4 * 96 + j]), tv0, a4);  b4 = ffma2(dup2(tat[4 * 96 + j + 1]), tv1, b4);
                a5 = ffma2(dup2(tat[5 * 96 + j]), tv0, a5);  b5 = ffma2(dup2(tat[5 * 96 + j + 1]), tv1, b5);
            }
            float2 fa0 = unpack2(a0), fb0 = unpack2(b0);
            float2 fa1 = unpack2(a1), fb1 = unpack2(b1);
            float2 fa2 = unpack2(a2), fb2 = unpack2(b2);
            float2 fa3 = unpack2(a3), fb3 = unpack2(b3);
            float2 fa4 = unpack2(a4), fb4 = unpack2(b4);
            float2 fa5 = unpack2(a5), fb5 = unpack2(b5);
            sm[K3_LO + (i0 + 0) * 64 + 2 * dp + 0] = tanhfast(fa0.x + fb0.x);
            sm[K3_LO + (i0 + 0) * 64 + 2 * dp + 1] = tanhfast(fa0.y + fb0.y);
            sm[K3_LO + (i0 + 1) * 64 + 2 * dp + 0] = tanhfast(fa1.x + fb1.x);
            sm[K3_LO + (i0 + 1) * 64 + 2 * dp + 1] = tanhfast(fa1.y + fb1.y);
            sm[K3_LO + (i0 + 2) * 64 + 2 * dp + 0] = tanhfast(fa2.x + fb2.x);
            sm[K3_LO + (i0 + 2) * 64 + 2 * dp + 1] = tanhfast(fa2.y + fb2.y);
            sm[K3_LO + (i0 + 3) * 64 + 2 * dp + 0] = tanhfast(fa3.x + fb3.x);
            sm[K3_LO + (i0 + 3) * 64 + 2 * dp + 1] = tanhfast(fa3.y + fb3.y);
            sm[K3_LO + (i0 + 4) * 64 + 2 * dp + 0] = tanhfast(fa4.x + fb4.x);
            sm[K3_LO + (i0 + 4) * 64 + 2 * dp + 1] = tanhfast(fa4.y + fb4.y);
            sm[K3_LO + (i0 + 5) * 64 + 2 * dp + 0] = tanhfast(fa5.x + fb5.x);
            sm[K3_LO + (i0 + 5) * 64 + 2 * dp + 1] = tanhfast(fa5.y + fb5.y);
        }
    }
    __syncthreads();

    // xg2[s,g] = to[s] . l2_wih[g] + bih[g] + bhh[g] -> gmem
    for (int idx = t; idx < 64 * 64; idx += K3_NT) {
        int row = idx >> 6, col = idx & 63;
        sm[K3_U + row * 68 + col] = P.l2_wih[idx];
    }
    __syncthreads();
    {
        int g2 = t & 63, sb = t >> 6;
        u64 wpk[32];
        const u64* wr = (const u64*)(sm + K3_U + g2 * 68);
#pragma unroll
        for (int k = 0; k < 32; k++) wpk[k] = wr[k];
        float bi = P.l2_bih[g2] + P.l2_bhh[g2];
        float* xgp = g_xg + (size_t)b * (Sn * Hn);
        for (int s24 = 0; s24 < 24; s24++) {
            int s = sb * 24 + s24;
            xgp[s * 64 + g2] = bi + dot64_pk(sm + K3_LO + s * 64, wpk);
        }
    }
}

// =========================== K4: LSTM2 recurrence + FC, warp-per-batch ===========================
struct P4 { const float *l2_whh, *fc_w, *fc_b; float* out; };

__global__ void __launch_bounds__(256) k4_rec(P4 P) {
    const int warp = blockIdx.x * 8 + (threadIdx.x >> 5);
    const int lane = threadIdx.x & 31;
    const float* xg = g_xg + (size_t)warp * (Sn * Hn);
    float* outp = P.out + (size_t)warp * (Sn * Dn);

    u64 w0[8], w1[8];
    {
        const u64* r0 = (const u64*)(P.l2_whh + lane * 16);
        const u64* r1 = (const u64*)(P.l2_whh + (lane + 32) * 16);
#pragma unroll
        for (int k = 0; k < 8; k++) { w0[k] = r0[k]; w1[k] = r1[k]; }
    }
    u64 wfc[8]; float fcb;
    {
        int fl = lane < 7 ? lane : 0;
        const u64* rf = (const u64*)(P.fc_w + fl * 16);
#pragma unroll
        for (int k = 0; k < 8; k++) wfc[k] = rf[k];
        fcb = P.fc_b[fl];
    }

    float h = 0.0f, c = 0.0f;
    float xg0 = xg[lane], xg1 = xg[32 + lane];

#pragma unroll 1
    for (int s = 0; s < Sn; s++) {
        u64 acc0 = 0ull, acc1 = 0ull, accf = 0ull;
#pragma unroll
        for (int m = 0; m < 8; m++) {
            float ha = __shfl_sync(0xffffffffu, h, 2 * m);
            float hb = __shfl_sync(0xffffffffu, h, 2 * m + 1);
            u64 hp = pack2(ha, hb);
            acc0 = ffma2(hp, w0[m], acc0);
            acc1 = ffma2(hp, w1[m], acc1);
            accf = ffma2(hp, wfc[m], accf);
        }
        if (s > 0 && lane < 7) {
            float2 ff = unpack2(accf);
            outp[(s - 1) * 7 + lane] = fcb + ff.x + ff.y;
        }
        float2 f0 = unpack2(acc0), f1 = unpack2(acc1);
        float a0 = xg0 + f0.x + f0.y;
        float a1 = xg1 + f1.x + f1.y;
        if (s + 1 < Sn) {
            xg0 = xg[(s + 1) * 64 + lane];
            xg1 = xg[(s + 1) * 64 + 32 + lane];
        }
        int j = lane & 15;
        float iv = __shfl_sync(0xffffffffu, a0, j);
        float fv = __shfl_sync(0xffffffffu, a0, j + 16);
        float gv = __shfl_sync(0xffffffffu, a1, j);
        float ov = __shfl_sync(0xffffffffu, a1, j + 16);
        c = sigf(fv) * c + sigf(iv) * tanhfast(gv);
        h = sigf(ov) * tanhfast(c);
    }
    {
        u64 accf = 0ull;
#pragma unroll
        for (int m = 0; m < 8; m++) {
            float ha = __shfl_sync(0xffffffffu, h, 2 * m);
            float hb = __shfl_sync(0xffffffffu, h, 2 * m + 1);
            accf = ffma2(pack2(ha, hb), wfc[m], accf);
        }
        if (lane < 7) {
            float2 ff = unpack2(accf);
            outp[95 * 7 + lane] = fcb + ff.x + ff.y;
        }
    }
}

// =========================== launch ===========================
extern "C" void kernel_launch(void* const* d_in, const int* in_sizes, int n_in,
                              void* d_out, int out_size) {
    P1 p1; P2 p2; P3 p3; P4 p4;
    p1.x       = (const float*)d_in[0];
    p1.fv_w    = (const float*)d_in[1];  p1.fv_b = (const float*)d_in[2];
    p1.fk_w    = (const float*)d_in[3];  p1.fk_b = (const float*)d_in[4];
    p1.fq_w    = (const float*)d_in[5];  p1.fq_b = (const float*)d_in[6];
    p2.l1f_wih = (const float*)d_in[7];  p2.l1f_whh = (const float*)d_in[8];
    p2.l1f_bih = (const float*)d_in[9];  p2.l1f_bhh = (const float*)d_in[10];
    p2.l1b_wih = (const float*)d_in[11]; p2.l1b_whh = (const float*)d_in[12];
    p2.l1b_bih = (const float*)d_in[13]; p2.l1b_bhh = (const float*)d_in[14];
    p3.tv_w    = (const float*)d_in[15]; p3.tv_b = (const float*)d_in[16];
    const float* tk_w = (const float*)d_in[17];
    const float* tq_w = (const float*)d_in[19];
    const float* tq_b = (const float*)d_in[20];
    p3.l2_wih  = (const float*)d_in[21];
    p3.l2_bih  = (const float*)d_in[23]; p3.l2_bhh = (const float*)d_in[24];
    p4.l2_whh  = (const float*)d_in[22];
    p4.fc_w    = (const float*)d_in[25]; p4.fc_b = (const float*)d_in[26];
    p4.out     = (float*)d_out;

    static cudaStream_t s1 = nullptr, s2 = nullptr;
    static cudaEvent_t eF = nullptr, eA = nullptr, eB = nullptr;
    if (s1 == nullptr) {
        cudaStreamCreateWithFlags(&s1, cudaStreamNonBlocking);
        cudaStreamCreateWithFlags(&s2, cudaStreamNonBlocking);
        cudaEventCreateWithFlags(&eF, cudaEventDisableTiming);
        cudaEventCreateWithFlags(&eA, cudaEventDisableTiming);
        cudaEventCreateWithFlags(&eB, cudaEventDisableTiming);
        cudaFuncSetAttribute(k3_tempatt, cudaFuncAttributeMaxDynamicSharedMemorySize,
                             K3_FLOATS * (int)sizeof(float));
    }

    const int Bh = Bn / 2;
    const int smem3 = K3_FLOATS * (int)sizeof(float);

    k0_prep<<<16, 256>>>(tq_w, tk_w, tq_b);
    k1_featatt<<<Bn, 128>>>(p1);
    cudaEventRecord(eF, 0);

    cudaStreamWaitEvent(s1, eF, 0);
    cudaStreamWaitEvent(s2, eF, 0);

    P2 p2a = p2; p2a.b0 = 0;
    P2 p2b = p2; p2b.b0 = Bh;
    P3 p3a = p3; p3a.b0 = 0;
    P3 p3b = p3; p3b.b0 = Bh;

    k2_bilstm<<<dim3(Bh / NJ, 2), 256, 0, s1>>>(p2a);
    k2_bilstm<<<dim3(Bh / NJ, 2), 256, 0, s2>>>(p2b);
    k3_tempatt<<<Bh, K3_NT, smem3, s1>>>(p3a);
    k3_tempatt<<<Bh, K3_NT, smem3, s2>>>(p3b);
    cudaEventRecord(eA, s1);
    cudaEventRecord(eB, s2);

    cudaStreamWaitEvent(0, eA, 0);
    cudaStreamWaitEvent(0, eB, 0);
    k4_rec<<<Bn / 8, 256>>>(p4);
}

// round 17
// speedup vs baseline: 3.0526x; 2.1852x over previous
#include <cuda_runtime.h>

// ---------------------------------------------------------------------------
// ftat_BiLSTM — round 17: R15 bodies, with K1 fused into K2's prologue
// (K1 kernel + g_fa eliminated -> no serial head, narrower graph: 7 nodes).
// K0 overlaps K2 and gates only K3. K4 per-half in-stream (R13 precedent).
// ---------------------------------------------------------------------------

namespace {
constexpr int Bn = 2048, Sn = 96, Dn = 7, Hn = 64;
constexpr int NJ = 4;
using u64 = unsigned long long;
} // namespace

__device__ float g_lof[Bn * Sn * Hn];
__device__ float g_lob[Bn * Sn * Hn];
__device__ float g_xg [Bn * Sn * Hn];
__device__ float g_M  [64 * 64];   // Wq^T Wk
__device__ float g_v  [64];        // Wk^T bq

__device__ __forceinline__ float sigf(float x) { return 1.0f / (1.0f + __expf(-x)); }
__device__ __forceinline__ float tanhfast(float x) { return 1.0f - 2.0f / (__expf(2.0f * x) + 1.0f); }

__device__ __forceinline__ u64 ffma2(u64 a, u64 b, u64 c) {
    u64 d; asm("fma.rn.f32x2 %0, %1, %2, %3;" : "=l"(d) : "l"(a), "l"(b), "l"(c)); return d;
}
__device__ __forceinline__ float2 unpack2(u64 v) {
    float2 r; asm("mov.b64 {%0, %1}, %2;" : "=f"(r.x), "=f"(r.y) : "l"(v)); return r;
}
__device__ __forceinline__ u64 pack2(float lo, float hi) {
    u64 v; asm("mov.b64 %0, {%1, %2};" : "=l"(v) : "f"(lo), "f"(hi)); return v;
}
__device__ __forceinline__ u64 dup2(float x) {
    u64 v; asm("mov.b64 %0, {%1, %1};" : "=l"(v) : "f"(x)); return v;
}

__device__ __forceinline__ float dot64_pk(const float* __restrict__ x, const u64* __restrict__ w) {
    u64 a0 = 0ull, a1 = 0ull, a2 = 0ull, a3 = 0ull;
    const float4* x4 = (const float4*)x;
#pragma unroll
    for (int j = 0; j < 16; j += 2) {
        float4 v0 = x4[j], v1 = x4[j + 1];
        a0 = ffma2(pack2(v0.x, v0.y), w[2 * j + 0], a0);
        a1 = ffma2(pack2(v0.z, v0.w), w[2 * j + 1], a1);
        a2 = ffma2(pack2(v1.x, v1.y), w[2 * j + 2], a2);
        a3 = ffma2(pack2(v1.z, v1.w), w[2 * j + 3], a3);
    }
    float2 f0 = unpack2(a0), f1 = unpack2(a1), f2 = unpack2(a2), f3 = unpack2(a3);
    return ((f0.x + f0.y) + (f1.x + f1.y)) + ((f2.x + f2.y) + (f3.x + f3.y));
}

// =========================== K0: precompute M = Wq^T Wk, v = Wk^T bq ===========================
__global__ void __launch_bounds__(256) k0_prep(const float* __restrict__ tq_w,
                                               const float* __restrict__ tk_w,
                                               const float* __restrict__ tq_b) {
    int idx = blockIdx.x * 256 + threadIdx.x;   // 0..4095
    int e = idx >> 6, f = idx & 63;
    float acc = 0.0f;
    for (int d = 0; d < 64; d++) acc += tq_w[d * 64 + e] * tk_w[d * 64 + f];
    g_M[idx] = acc;
    if (idx < 64) {
        float a = 0.0f;
        for (int d = 0; d < 64; d++) a += tq_b[d] * tk_w[d * 64 + idx];
        g_v[idx] = a;
    }
}

// =========================== K2: fused feature-attention + BiLSTM ===========================
struct P2 {
    const float *x;
    const float *fv_w, *fv_b, *fk_w, *fk_b, *fq_w, *fq_b;
    const float *l1f_wih, *l1f_whh, *l1f_bih, *l1f_bhh;
    const float *l1b_wih, *l1b_whh, *l1b_bih, *l1b_bhh;
    int b0;
};

__global__ void __launch_bounds__(256, 2) k2_bilstm(P2 P) {
    __shared__ __align__(16) float sFA[NJ][Sn * 8];   // 12 KB (x -> fa in place)
    __shared__ __align__(16) float sWST[64 * 68];     // 17.4 KB
    __shared__ __align__(16) float sH[NJ][Hn];        // 1 KB
    __shared__ float sG[NJ][256];                     // 4 KB
    __shared__ __align__(16) float sV[Sn * 8];        // 3 KB (prologue scratch)
    __shared__ __align__(16) float sK[Sn * 8];        // 3 KB
    __shared__ __align__(16) float sQ[Sn * 8];        // 3 KB
    __shared__ float sATT[7 * 8];
    const int dir = blockIdx.y, t = threadIdx.x;
    const int bbase = P.b0 + NJ * blockIdx.x;

    // ---------- prologue: feature attention for the 4 jobs (was K1) ----------
    // load x for all jobs, padded stride 8
    for (int idx = t; idx < NJ * Sn * Dn; idx += 256) {
        int jj = idx / (Sn * Dn), r = idx - jj * (Sn * Dn);
        int s = r / 7, j = r - s * 7;
        sFA[jj][s * 8 + j] = P.x[(size_t)(bbase + jj) * (Sn * Dn) + r];
    }
    for (int idx = t; idx < NJ * Sn; idx += 256) {
        int jj = idx / Sn, s = idx - jj * Sn;
        sFA[jj][s * 8 + 7] = 0.0f;
    }
    __syncthreads();

#pragma unroll 1
    for (int jj = 0; jj < NJ; jj++) {
        for (int idx = t; idx < Sn * Dn; idx += 256) {
            int s = idx / 7, i = idx - s * 7;
            float a = P.fv_b[i];
#pragma unroll
            for (int j = 0; j < 7; j++) a += sFA[jj][s * 8 + j] * P.fv_w[i * 7 + j];
            sV[s * 8 + i] = a;
        }
        __syncthreads();
        for (int idx = t; idx < Sn * Dn; idx += 256) {
            int s = idx / 7, i = idx - s * 7;
            float a = P.fk_b[i];
#pragma unroll
            for (int j = 0; j < 7; j++) a += (sFA[jj][s * 8 + j] + sV[s * 8 + j]) * P.fk_w[i * 7 + j];
            sK[s * 8 + i] = a;
        }
        __syncthreads();
        for (int idx = t; idx < Sn * Dn; idx += 256) {
            int s = idx / 7, i = idx - s * 7;
            float a = P.fq_b[i];
#pragma unroll
            for (int j = 0; j < 7; j++) a += (sFA[jj][s * 8 + j] + sK[s * 8 + j]) * P.fq_w[i * 7 + j];
            sQ[s * 8 + i] = a;
        }
        __syncthreads();
        // logits: 49 pairs x 2 threads (48 s-terms each) + shfl combine
        if (t < 98) {
            int pair = t >> 1, half = t & 1;
            int i = pair / 7, j = pair - (pair / 7) * 7;
            float a = 0.0f;
            int s0 = half * 48;
#pragma unroll 8
            for (int s = s0; s < s0 + 48; s++) a += sQ[s * 8 + i] * sK[s * 8 + j];
            unsigned mask = (t < 96) ? 0xffffffffu : 0x00000003u;
            a += __shfl_xor_sync(mask, a, 1);
            if (half == 0) sATT[i * 8 + j] = a;
        }
        __syncthreads();
        if (t < 7) {
            float* row = sATT + t * 8;
            float m = row[0];
#pragma unroll
            for (int j = 1; j < 7; j++) m = fmaxf(m, row[j]);
            float ssum = 0.0f;
#pragma unroll
            for (int j = 0; j < 7; j++) { float e = __expf(row[j] - m); row[j] = e; ssum += e; }
            float inv = 1.0f / ssum;
#pragma unroll
            for (int j = 0; j < 7; j++) row[j] *= inv;
        }
        __syncthreads();
        for (int idx = t; idx < Sn * Dn; idx += 256) {
            int s = idx / 7, j = idx - s * 7;
            float a = sFA[jj][s * 8 + j];
#pragma unroll
            for (int i = 0; i < 7; i++) a += sV[s * 8 + i] * sATT[i * 8 + j];
            sFA[jj][s * 8 + j] = tanhfast(a);
        }
        __syncthreads();
    }

    // ---------- BiLSTM (R10/R15 hot loop, unchanged) ----------
    const float* whh = dir ? P.l1b_whh : P.l1f_whh;
    u64 wpk[32];
#pragma unroll 1
    for (int r = 0; r < 4; r++) {
        for (int idx = t; idx < 64 * 64; idx += 256) {
            int row = idx >> 6, col = idx & 63;
            sWST[row * 68 + col] = whh[(r * 64 + row) * 64 + col];
        }
        __syncthreads();
        if ((t >> 6) == r) {
            const u64* wr = (const u64*)(sWST + (t & 63) * 68);
#pragma unroll
            for (int k = 0; k < 32; k++) wpk[k] = wr[k];
        }
        __syncthreads();
    }
    float wi[7], bias;
    {
        const float* wih = dir ? P.l1b_wih : P.l1f_wih;
#pragma unroll
        for (int j = 0; j < 7; j++) wi[j] = wih[t * 7 + j];
        bias = dir ? (P.l1b_bih[t] + P.l1b_bhh[t]) : (P.l1f_bih[t] + P.l1f_bhh[t]);
    }
    const int jjA = t >> 6, uA = t & 63;
    ((float*)sH)[t] = 0.0f;
    float c1 = 0.0f;
    __syncthreads();

    float* loA = (dir ? g_lob : g_lof) + (size_t)(bbase + jjA) * (Sn * Hn);

#pragma unroll 1
    for (int step = 0; step < Sn; step++) {
        const int s = dir ? (Sn - 1 - step) : step;
#pragma unroll
        for (int jj = 0; jj < NJ; jj++) {
            u64 a0 = 0ull, a1 = 0ull, a2 = 0ull, a3 = 0ull;
            const float4* h4 = (const float4*)sH[jj];
#pragma unroll
            for (int q = 0; q < 16; q += 2) {
                float4 v0 = h4[q], v1 = h4[q + 1];
                a0 = ffma2(pack2(v0.x, v0.y), wpk[2 * q + 0], a0);
                a1 = ffma2(pack2(v0.z, v0.w), wpk[2 * q + 1], a1);
                a2 = ffma2(pack2(v1.x, v1.y), wpk[2 * q + 2], a2);
                a3 = ffma2(pack2(v1.z, v1.w), wpk[2 * q + 3], a3);
            }
            float2 f0 = unpack2(a0), f1 = unpack2(a1), f2 = unpack2(a2), f3 = unpack2(a3);
            float a = bias + ((f0.x + f0.y) + (f1.x + f1.y)) + ((f2.x + f2.y) + (f3.x + f3.y));
            const float* fr = sFA[jj] + s * 8;
#pragma unroll
            for (int j = 0; j < 7; j++) a += fr[j] * wi[j];
            sG[jj][t] = a;
        }
        __syncthreads();
        {
            float gi = sG[jjA][uA], gf = sG[jjA][64 + uA];
            float gc = sG[jjA][128 + uA], go = sG[jjA][192 + uA];
            c1 = sigf(gf) * c1 + sigf(gi) * tanhfast(gc);
            float h = sigf(go) * tanhfast(c1);
            sH[jjA][uA] = h;
            loA[s * Hn + uA] = 0.5f * h;
        }
        __syncthreads();
    }
}

// =========================== K3: temporal attention + LSTM2-input GEMM ===========================
struct P3 {
    const float *tv_w, *tv_b;
    const float *l2_wih, *l2_bih, *l2_bhh;
    int b0;
};

namespace {
constexpr int K3_LO   = 0;
constexpr int K3_TV   = 6144;
constexpr int K3_U    = 12288;
constexpr int K3_TATT = 18816;
constexpr int K3_WST  = K3_TATT;
constexpr int K3_SA   = 28032;
constexpr int K3_SV   = 28128;
constexpr int K3_FLOATS = 28192;
constexpr int K3_NT   = 256;
}

__global__ void __launch_bounds__(256, 2) k3_tempatt(P3 P) {
    extern __shared__ float sm[];
    const int b = P.b0 + blockIdx.x, t = threadIdx.x;

    {
        const float* lf = g_lof + (size_t)b * (Sn * Hn);
        const float* lb = g_lob + (size_t)b * (Sn * Hn);
        for (int idx = t; idx < Sn * Hn; idx += K3_NT) sm[K3_LO + idx] = lf[idx] + lb[idx];
    }
    if (t < 64) sm[K3_SV + t] = g_v[t];
    __syncthreads();

    for (int idx = t; idx < 64 * 64; idx += K3_NT) {
        int row = idx >> 6, col = idx & 63;
        sm[K3_WST + row * 68 + col] = P.tv_w[idx];
    }
    if (t < 96) {
        const float4* lo4 = (const float4*)(sm + K3_LO + t * 64);
        const float4* v4 = (const float4*)(sm + K3_SV);
        float acc = 0.0f;
#pragma unroll
        for (int k = 0; k < 16; k++) {
            float4 l = lo4[k], vv = v4[k];
            acc += l.x * vv.x + l.y * vv.y + l.z * vv.z + l.w * vv.w;
        }
        sm[K3_SA + t] = acc;
    }
    __syncthreads();

    {
        int i = t & 63, sb = t >> 6;
        u64 wpk[32];
        const u64* wr = (const u64*)(sm + K3_WST + i * 68);
#pragma unroll
        for (int k = 0; k < 32; k++) wpk[k] = wr[k];
        float bi = P.tv_b[i];
        for (int s24 = 0; s24 < 24; s24++) {
            int s = sb * 24 + s24;
            sm[K3_TV + s * 64 + i] = bi + dot64_pk(sm + K3_LO + s * 64, wpk);
        }
    }
    __syncthreads();

    for (int idx = t; idx < 64 * 64; idx += K3_NT) {
        int row = idx >> 6, col = idx & 63;
        sm[K3_WST + row * 68 + col] = g_M[idx];
    }
    __syncthreads();

    {
        int i = t & 63, sb = t >> 6;
        u64 wpk[32];
        const u64* wr = (const u64*)(sm + K3_WST + i * 68);
#pragma unroll
        for (int k = 0; k < 32; k++) wpk[k] = wr[k];
        for (int s24 = 0; s24 < 24; s24++) {
            int s = sb * 24 + s24;
            sm[K3_U + s * 68 + i] = dot64_pk(sm + K3_LO + s * 64, wpk);
        }
    }
    __syncthreads();

#pragma unroll 1
    for (int r = 0; r < 6; r++) {
        int task = r * K3_NT + t;
        int ip = task / 96, j = task - ip * 96;
        int i0 = ip * 6;
        const float4* k4p = (const float4*)(sm + K3_U + j * 68);
        u64 acc0 = 0ull, acc1 = 0ull, acc2 = 0ull, acc3 = 0ull, acc4 = 0ull, acc5 = 0ull;
#pragma unroll
        for (int d4 = 0; d4 < 16; d4++) {
            float4 kv = k4p[d4];
            u64 k01 = pack2(kv.x, kv.y), k23 = pack2(kv.z, kv.w);
            float4 q0 = *(const float4*)(sm + K3_LO + (i0 + 0) * 64 + d4 * 4);
            float4 q1 = *(const float4*)(sm + K3_LO + (i0 + 1) * 64 + d4 * 4);
            float4 q2 = *(const float4*)(sm + K3_LO + (i0 + 2) * 64 + d4 * 4);
            float4 q3 = *(const float4*)(sm + K3_LO + (i0 + 3) * 64 + d4 * 4);
            float4 q4 = *(const float4*)(sm + K3_LO + (i0 + 4) * 64 + d4 * 4);
            float4 q5 = *(const float4*)(sm + K3_LO + (i0 + 5) * 64 + d4 * 4);
            acc0 = ffma2(pack2(q0.x, q0.y), k01, acc0); acc0 = ffma2(pack2(q0.z, q0.w), k23, acc0);
            acc1 = ffma2(pack2(q1.x, q1.y), k01, acc1); acc1 = ffma2(pack2(q1.z, q1.w), k23, acc1);
            acc2 = ffma2(pack2(q2.x, q2.y), k01, acc2); acc2 = ffma2(pack2(q2.z, q2.w), k23, acc2);
            acc3 = ffma2(pack2(q3.x, q3.y), k01, acc3); acc3 = ffma2(pack2(q3.z, q3.w), k23, acc3);
            acc4 = ffma2(pack2(q4.x, q4.y), k01, acc4); acc4 = ffma2(pack2(q4.z, q4.w), k23, acc4);
            acc5 = ffma2(pack2(q5.x, q5.y), k01, acc5); acc5 = ffma2(pack2(q5.z, q5.w), k23, acc5);
        }
        float aj = sm[K3_SA + j];
        float2 f0 = unpack2(acc0), f1 = unpack2(acc1), f2 = unpack2(acc2);
        float2 f3 = unpack2(acc3), f4 = unpack2(acc4), f5 = unpack2(acc5);
        sm[K3_TATT + (i0 + 0) * 96 + j] = f0.x + f0.y + aj;
        sm[K3_TATT + (i0 + 1) * 96 + j] = f1.x + f1.y + aj;
        sm[K3_TATT + (i0 + 2) * 96 + j] = f2.x + f2.y + aj;
        sm[K3_TATT + (i0 + 3) * 96 + j] = f3.x + f3.y + aj;
        sm[K3_TATT + (i0 + 4) * 96 + j] = f4.x + f4.y + aj;
        sm[K3_TATT + (i0 + 5) * 96 + j] = f5.x + f5.y + aj;
    }
    __syncthreads();

    {
        int w = t >> 5, lane = t & 31;
        for (int rr = 0; rr < 12; rr++) {
            int i = w * 12 + rr;
            float* row = sm + K3_TATT + i * 96;
            float v0 = row[lane], v1 = row[lane + 32], v2 = row[lane + 64];
            float m = fmaxf(v0, fmaxf(v1, v2));
#pragma unroll
            for (int off = 16; off > 0; off >>= 1) m = fmaxf(m, __shfl_xor_sync(0xffffffffu, m, off));
            float e0 = __expf(v0 - m), e1 = __expf(v1 - m), e2 = __expf(v2 - m);
            float ssum = e0 + e1 + e2;
#pragma unroll
            for (int off = 16; off > 0; off >>= 1) ssum += __shfl_xor_sync(0xffffffffu, ssum, off);
            float inv = 1.0f / ssum;
            row[lane] = e0 * inv; row[lane + 32] = e1 * inv; row[lane + 64] = e2 * inv;
        }
    }
    __syncthreads();

    {
        int dp = t & 31, wb = t >> 5;
        const float* tvcol = sm + K3_TV + 2 * dp;
#pragma unroll 1
        for (int i3 = 0; i3 < 2; i3++) {
            int i0 = wb * 12 + 6 * i3;
            const float* tat = sm + K3_TATT + i0 * 96;
            u64 a0 = 0ull, a1 = 0ull, a2 = 0ull, a3 = 0ull, a4 = 0ull, a5 = 0ull;
            u64 b0 = 0ull, b1 = 0ull, b2 = 0ull, b3 = 0ull, b4 = 0ull, b5 = 0ull;
#pragma unroll 4
            for (int j = 0; j < 96; j += 2) {
                u64 tv0 = *(const u64*)(tvcol + j * 64);
                u64 tv1 = *(const u64*)(tvcol + (j + 1) * 64);
                a0 = ffma2(dup2(tat[0 * 96 + j]), tv0, a0);  b0 = ffma2(dup2(tat[0 * 96 + j + 1]), tv1, b0);
                a1 = ffma2(dup2(tat[1 * 96 + j]), tv0, a1);  b1 = ffma2(dup2(tat[1 * 96 + j + 1]), tv1, b1);
                a2 = ffma2(dup2(tat[2 * 96 + j]), tv0, a2);  b2 = ffma2(dup2(tat[2 * 96 + j + 1]), tv1, b2);
                a3 = ffma2(dup2(tat[3 * 96 + j]), tv0, a3);  b3 = ffma2(dup2(tat[3 * 96 + j + 1]), tv1, b3);
                a4 = ffma2(dup2(tat[4 * 96 + j]), tv0, a4);  b4 = ffma2(dup2(tat[4 * 96 + j + 1]), tv1, b4);
                a5 = ffma2(dup2(tat[5 * 96 + j]), tv0, a5);  b5 = ffma2(dup2(tat[5 * 96 + j + 1]), tv1, b5);
            }
            float2 fa0 = unpack2(a0), fb0 = unpack2(b0);
            float2 fa1 = unpack2(a1), fb1 = unpack2(b1);
            float2 fa2 = unpack2(a2), fb2 = unpack2(b2);
            float2 fa3 = unpack2(a3), fb3 = unpack2(b3);
            float2 fa4 = unpack2(a4), fb4 = unpack2(b4);
            float2 fa5 = unpack2(a5), fb5 = unpack2(b5);
            sm[K3_LO + (i0 + 0) * 64 + 2 * dp + 0] = tanhfast(fa0.x + fb0.x);
            sm[K3_LO + (i0 + 0) * 64 + 2 * dp + 1] = tanhfast(fa0.y + fb0.y);
            sm[K3_LO + (i0 + 1) * 64 + 2 * dp + 0] = tanhfast(fa1.x + fb1.x);
            sm[K3_LO + (i0 + 1) * 64 + 2 * dp + 1] = tanhfast(fa1.y + fb1.y);
            sm[K3_LO + (i0 + 2) * 64 + 2 * dp + 0] = tanhfast(fa2.x + fb2.x);
            sm[K3_LO + (i0 + 2) * 64 + 2 * dp + 1] = tanhfast(fa2.y + fb2.y);
            sm[K3_LO + (i0 + 3) * 64 + 2 * dp + 0] = tanhfast(fa3.x + fb3.x);
            sm[K3_LO + (i0 + 3) * 64 + 2 * dp + 1] = tanhfast(fa3.y + fb3.y);
            sm[K3_LO + (i0 + 4) * 64 + 2 * dp + 0] = tanhfast(fa4.x + fb4.x);
            sm[K3_LO + (i0 + 4) * 64 + 2 * dp + 1] = tanhfast(fa4.y + fb4.y);
            sm[K3_LO + (i0 + 5) * 64 + 2 * dp + 0] = tanhfast(fa5.x + fb5.x);
            sm[K3_LO + (i0 + 5) * 64 + 2 * dp + 1] = tanhfast(fa5.y + fb5.y);
        }
    }
    __syncthreads();

    for (int idx = t; idx < 64 * 64; idx += K3_NT) {
        int row = idx >> 6, col = idx & 63;
        sm[K3_U + row * 68 + col] = P.l2_wih[idx];
    }
    __syncthreads();
    {
        int g2 = t & 63, sb = t >> 6;
        u64 wpk[32];
        const u64* wr = (const u64*)(sm + K3_U + g2 * 68);
#pragma unroll
        for (int k = 0; k < 32; k++) wpk[k] = wr[k];
        float bi = P.l2_bih[g2] + P.l2_bhh[g2];
        float* xgp = g_xg + (size_t)b * (Sn * Hn);
        for (int s24 = 0; s24 < 24; s24++) {
            int s = sb * 24 + s24;
            xgp[s * 64 + g2] = bi + dot64_pk(sm + K3_LO + s * 64, wpk);
        }
    }
}

// =========================== K4: LSTM2 recurrence + FC, warp-per-batch ===========================
struct P4 { const float *l2_whh, *fc_w, *fc_b; float* out; int b0; };

__global__ void __launch_bounds__(256) k4_rec(P4 P) {
    const int warp = P.b0 + blockIdx.x * 8 + (threadIdx.x >> 5);
    const int lane = threadIdx.x & 31;
    const float* xg = g_xg + (size_t)warp * (Sn * Hn);
    float* outp = P.out + (size_t)warp * (Sn * Dn);

    u64 w0[8], w1[8];
    {
        const u64* r0 = (const u64*)(P.l2_whh + lane * 16);
        const u64* r1 = (const u64*)(P.l2_whh + (lane + 32) * 16);
#pragma unroll
        for (int k = 0; k < 8; k++) { w0[k] = r0[k]; w1[k] = r1[k]; }
    }
    u64 wfc[8]; float fcb;
    {
        int fl = lane < 7 ? lane : 0;
        const u64* rf = (const u64*)(P.fc_w + fl * 16);
#pragma unroll
        for (int k = 0; k < 8; k++) wfc[k] = rf[k];
        fcb = P.fc_b[fl];
    }

    float h = 0.0f, c = 0.0f;
    float xg0 = xg[lane], xg1 = xg[32 + lane];

#pragma unroll 1
    for (int s = 0; s < Sn; s++) {
        u64 acc0 = 0ull, acc1 = 0ull, accf = 0ull;
#pragma unroll
        for (int m = 0; m < 8; m++) {
            float ha = __shfl_sync(0xffffffffu, h, 2 * m);
            float hb = __shfl_sync(0xffffffffu, h, 2 * m + 1);
            u64 hp = pack2(ha, hb);
            acc0 = ffma2(hp, w0[m], acc0);
            acc1 = ffma2(hp, w1[m], acc1);
            accf = ffma2(hp, wfc[m], accf);
        }
        if (s > 0 && lane < 7) {
            float2 ff = unpack2(accf);
            outp[(s - 1) * 7 + lane] = fcb + ff.x + ff.y;
        }
        float2 f0 = unpack2(acc0), f1 = unpack2(acc1);
        float a0 = xg0 + f0.x + f0.y;
        float a1 = xg1 + f1.x + f1.y;
        if (s + 1 < Sn) {
            xg0 = xg[(s + 1) * 64 + lane];
            xg1 = xg[(s + 1) * 64 + 32 + lane];
        }
        int j = lane & 15;
        float iv = __shfl_sync(0xffffffffu, a0, j);
        float fv = __shfl_sync(0xffffffffu, a0, j + 16);
        float gv = __shfl_sync(0xffffffffu, a1, j);
        float ov = __shfl_sync(0xffffffffu, a1, j + 16);
        c = sigf(fv) * c + sigf(iv) * tanhfast(gv);
        h = sigf(ov) * tanhfast(c);
    }
    {
        u64 accf = 0ull;
#pragma unroll
        for (int m = 0; m < 8; m++) {
            float ha = __shfl_sync(0xffffffffu, h, 2 * m);
            float hb = __shfl_sync(0xffffffffu, h, 2 * m + 1);
            accf = ffma2(pack2(ha, hb), wfc[m], accf);
        }
        if (lane < 7) {
            float2 ff = unpack2(accf);
            outp[95 * 7 + lane] = fcb + ff.x + ff.y;
        }
    }
}

// =========================== launch ===========================
extern "C" void kernel_launch(void* const* d_in, const int* in_sizes, int n_in,
                              void* d_out, int out_size) {
    P2 p2; P3 p3; P4 p4;
    p2.x       = (const float*)d_in[0];
    p2.fv_w    = (const float*)d_in[1];  p2.fv_b = (const float*)d_in[2];
    p2.fk_w    = (const float*)d_in[3];  p2.fk_b = (const float*)d_in[4];
    p2.fq_w    = (const float*)d_in[5];  p2.fq_b = (const float*)d_in[6];
    p2.l1f_wih = (const float*)d_in[7];  p2.l1f_whh = (const float*)d_in[8];
    p2.l1f_bih = (const float*)d_in[9];  p2.l1f_bhh = (const float*)d_in[10];
    p2.l1b_wih = (const float*)d_in[11]; p2.l1b_whh = (const float*)d_in[12];
    p2.l1b_bih = (const float*)d_in[13]; p2.l1b_bhh = (const float*)d_in[14];
    p3.tv_w    = (const float*)d_in[15]; p3.tv_b = (const float*)d_in[16];
    const float* tk_w = (const float*)d_in[17];
    const float* tq_w = (const float*)d_in[19];
    const float* tq_b = (const float*)d_in[20];
    p3.l2_wih  = (const float*)d_in[21];
    p3.l2_bih  = (const float*)d_in[23]; p3.l2_bhh = (const float*)d_in[24];
    p4.l2_whh  = (const float*)d_in[22];
    p4.fc_w    = (const float*)d_in[25]; p4.fc_b = (const float*)d_in[26];
    p4.out     = (float*)d_out;

    static cudaStream_t s1 = nullptr, s2 = nullptr;
    static cudaEvent_t e0 = nullptr, eA = nullptr, eB = nullptr;
    if (s1 == nullptr) {
        cudaStreamCreateWithFlags(&s1, cudaStreamNonBlocking);
        cudaStreamCreateWithFlags(&s2, cudaStreamNonBlocking);
        cudaEventCreateWithFlags(&e0, cudaEventDisableTiming);
        cudaEventCreateWithFlags(&eA, cudaEventDisableTiming);
        cudaEventCreateWithFlags(&eB, cudaEventDisableTiming);
        cudaFuncSetAttribute(k3_tempatt, cudaFuncAttributeMaxDynamicSharedMemorySize,
                             K3_FLOATS * (int)sizeof(float));
    }

    const int Bh = Bn / 2;
    const int smem3 = K3_FLOATS * (int)sizeof(float);

    // k0 only gates K3 (g_M, g_v); it overlaps the K2s.
    k0_prep<<<16, 256>>>(tq_w, tk_w, tq_b);
    cudaEventRecord(e0, 0);

    P2 p2a = p2; p2a.b0 = 0;
    P2 p2b = p2; p2b.b0 = Bh;
    P3 p3a = p3; p3a.b0 = 0;
    P3 p3b = p3; p3b.b0 = Bh;
    P4 p4a = p4; p4a.b0 = 0;
    P4 p4b = p4; p4b.b0 = Bh;

    k2_bilstm<<<dim3(Bh / NJ, 2), 256, 0, s1>>>(p2a);
    k2_bilstm<<<dim3(Bh / NJ, 2), 256, 0, s2>>>(p2b);
    cudaStreamWaitEvent(s1, e0, 0);
    cudaStreamWaitEvent(s2, e0, 0);
    k3_tempatt<<<Bh, K3_NT, smem3, s1>>>(p3a);
    k3_tempatt<<<Bh, K3_NT, smem3, s2>>>(p3b);
    k4_rec<<<Bh / 8, 256, 0, s1>>>(p4a);
    k4_rec<<<Bh / 8, 256, 0, s2>>>(p4b);
    cudaEventRecord(eA, s1);
    cudaEventRecord(eB, s2);

    cudaStreamWaitEvent(0, eA, 0);
    cudaStreamWaitEvent(0, eB, 0);
}